// round 1
// baseline (speedup 1.0000x reference)
#include <cuda_runtime.h>

// Problem constants (fixed by setup_inputs)
#define B_  64
#define NO_ 1024
#define NI_ 1024

// RHO_R = exp(-DT/TAU_R) = exp(-0.001/0.02) = exp(-0.05)
__device__ __constant__ float kRhoR = 0.95122942450071400910f;
// THR = 1.0

// One block per (b, j) pair. 256 threads x float4 = 1024 = NI elements.
__global__ void __launch_bounds__(256, 8)
hetsyn_cell_kernel(const float* __restrict__ x,      // (B, NI)
                   const float* __restrict__ w,      // (NO, NI)
                   const float* __restrict__ rho,    // (NO, NI)
                   const float* __restrict__ hz,     // (B, NO)
                   const float* __restrict__ hIsyn,  // (B, NO, NI)
                   const float* __restrict__ hIr,    // (B, NO)
                   float* __restrict__ z_out,        // (B, NO)
                   float* __restrict__ Isyn_out,     // (B, NO, NI)
                   float* __restrict__ Ir_out)       // (B, NO)
{
    const int bid = blockIdx.x;        // b * NO + j
    const int b   = bid >> 10;         // / NO_
    const int j   = bid & (NO_ - 1);   // % NO_
    const int t   = threadIdx.x;       // 0..255

    const size_t row  = (size_t)bid * NI_;   // hIsyn / Isyn row
    const size_t wrow = (size_t)j   * NI_;   // w / rho row
    const size_t xrow = (size_t)b   * NI_;   // x row

    // Vectorized element work: Isyn = rho*hIsyn + w*x
    const float4 hv = __ldcs(reinterpret_cast<const float4*>(hIsyn + row)  + t); // stream
    const float4 rv = __ldg (reinterpret_cast<const float4*>(rho   + wrow) + t); // L2-resident
    const float4 wv = __ldg (reinterpret_cast<const float4*>(w     + wrow) + t); // L2-resident
    const float4 xv = __ldg (reinterpret_cast<const float4*>(x     + xrow) + t); // L2-resident

    float4 Is;
    Is.x = fmaf(rv.x, hv.x, wv.x * xv.x);
    Is.y = fmaf(rv.y, hv.y, wv.y * xv.y);
    Is.z = fmaf(rv.z, hv.z, wv.z * xv.z);
    Is.w = fmaf(rv.w, hv.w, wv.w * xv.w);

    __stcs(reinterpret_cast<float4*>(Isyn_out + row) + t, Is);  // write-only stream

    // Row reduction: per-thread partial
    float s = (Is.x + Is.y) + (Is.z + Is.w);

    // Warp reduce
    #pragma unroll
    for (int off = 16; off > 0; off >>= 1)
        s += __shfl_down_sync(0xFFFFFFFFu, s, off);

    // Cross-warp via smem (8 warps)
    __shared__ float warp_sums[8];
    const int lane = t & 31;
    const int warp = t >> 5;
    if (lane == 0) warp_sums[warp] = s;
    __syncthreads();

    if (t == 0) {
        float v_in = 0.0f;
        #pragma unroll
        for (int k = 0; k < 8; ++k) v_in += warp_sums[k];

        const float Ir = fmaf(kRhoR, hIr[bid], hz[bid]);
        const float v  = v_in - Ir;               // THR * Ir, THR = 1
        Ir_out[bid] = Ir;
        z_out[bid]  = (v - 1.0f >= 0.0f) ? 1.0f : 0.0f;  // spike(v - THR)
    }
}

extern "C" void kernel_launch(void* const* d_in, const int* in_sizes, int n_in,
                              void* d_out, int out_size)
{
    // Input order per setup_inputs: x, w, rho, hz, hIsyn, hIr
    const float* x     = (const float*)d_in[0];
    const float* w     = (const float*)d_in[1];
    const float* rho   = (const float*)d_in[2];
    const float* hz    = (const float*)d_in[3];
    const float* hIsyn = (const float*)d_in[4];
    const float* hIr   = (const float*)d_in[5];

    // Output tuple (z, Isyn, Ir) flattened + concatenated
    float* out    = (float*)d_out;
    float* z_out  = out;
    float* Isyn_o = out + (size_t)B_ * NO_;
    float* Ir_out = out + (size_t)B_ * NO_ + (size_t)B_ * NO_ * NI_;

    dim3 grid(B_ * NO_);   // 65536 blocks, one per (b, j)
    dim3 block(256);
    hetsyn_cell_kernel<<<grid, block>>>(x, w, rho, hz, hIsyn, hIr,
                                        z_out, Isyn_o, Ir_out);
}

// round 2
// speedup vs baseline: 1.0191x; 1.0191x over previous
#include <cuda_runtime.h>

// Problem constants (fixed by setup_inputs)
#define B_  64
#define NO_ 1024
#define NI_ 1024
#define NB  8          // batches per block

// RHO_R = exp(-DT/TAU_R) = exp(-0.05)
__device__ __constant__ float kRhoR = 0.95122942450071400910f;

// Block = (j, tile of NB batches). 256 threads x float4 = 1024 = NI.
// rho/w row loaded ONCE into registers, reused across NB batches.
// NB independent load->fma->store chains per thread => high MLP.
__global__ void __launch_bounds__(256)
hetsyn_cell_kernel(const float* __restrict__ x,      // (B, NI)
                   const float* __restrict__ w,      // (NO, NI)
                   const float* __restrict__ rho,    // (NO, NI)
                   const float* __restrict__ hz,     // (B, NO)
                   const float* __restrict__ hIsyn,  // (B, NO, NI)
                   const float* __restrict__ hIr,    // (B, NO)
                   float* __restrict__ z_out,        // (B, NO)
                   float* __restrict__ Isyn_out,     // (B, NO, NI)
                   float* __restrict__ Ir_out)       // (B, NO)
{
    const int j  = blockIdx.x;          // output neuron row
    const int b0 = blockIdx.y * NB;     // first batch of this tile
    const int t  = threadIdx.x;         // 0..255

    const size_t wrow = (size_t)j * NI_;
    const float4 rv = __ldg(reinterpret_cast<const float4*>(rho + wrow) + t);
    const float4 wv = __ldg(reinterpret_cast<const float4*>(w   + wrow) + t);

    float psum[NB];

    #pragma unroll
    for (int bb = 0; bb < NB; ++bb) {
        const int b = b0 + bb;
        const size_t row = ((size_t)b * NO_ + j) * (size_t)NI_;

        const float4 hv = __ldcs(reinterpret_cast<const float4*>(hIsyn + row) + t);
        const float4 xv = __ldg (reinterpret_cast<const float4*>(x + (size_t)b * NI_) + t);

        float4 Is;
        Is.x = fmaf(rv.x, hv.x, wv.x * xv.x);
        Is.y = fmaf(rv.y, hv.y, wv.y * xv.y);
        Is.z = fmaf(rv.z, hv.z, wv.z * xv.z);
        Is.w = fmaf(rv.w, hv.w, wv.w * xv.w);

        __stcs(reinterpret_cast<float4*>(Isyn_out + row) + t, Is);

        psum[bb] = (Is.x + Is.y) + (Is.z + Is.w);
    }

    // Warp-level reduction of each of the NB partial sums
    #pragma unroll
    for (int bb = 0; bb < NB; ++bb) {
        #pragma unroll
        for (int off = 16; off > 0; off >>= 1)
            psum[bb] += __shfl_down_sync(0xFFFFFFFFu, psum[bb], off);
    }

    __shared__ float wsum[8][NB];   // [warp][batch]
    const int lane = t & 31;
    const int warp = t >> 5;
    if (lane == 0) {
        #pragma unroll
        for (int bb = 0; bb < NB; ++bb) wsum[warp][bb] = psum[bb];
    }
    __syncthreads();

    if (t < NB) {
        float v_in = 0.0f;
        #pragma unroll
        for (int k = 0; k < 8; ++k) v_in += wsum[k][t];

        const int b    = b0 + t;
        const int oidx = b * NO_ + j;

        const float Ir = fmaf(kRhoR, hIr[oidx], hz[oidx]);
        Ir_out[oidx] = Ir;
        // v = v_in - THR*Ir; z = (v - THR >= 0), THR = 1
        z_out[oidx]  = (v_in - Ir - 1.0f >= 0.0f) ? 1.0f : 0.0f;
    }
}

extern "C" void kernel_launch(void* const* d_in, const int* in_sizes, int n_in,
                              void* d_out, int out_size)
{
    // Input order per setup_inputs: x, w, rho, hz, hIsyn, hIr
    const float* x     = (const float*)d_in[0];
    const float* w     = (const float*)d_in[1];
    const float* rho   = (const float*)d_in[2];
    const float* hz    = (const float*)d_in[3];
    const float* hIsyn = (const float*)d_in[4];
    const float* hIr   = (const float*)d_in[5];

    // Output tuple (z, Isyn, Ir) flattened + concatenated
    float* out    = (float*)d_out;
    float* z_out  = out;
    float* Isyn_o = out + (size_t)B_ * NO_;
    float* Ir_out = out + (size_t)B_ * NO_ + (size_t)B_ * NO_ * NI_;

    dim3 grid(NO_, B_ / NB);   // (1024, 8) = 8192 blocks
    dim3 block(256);
    hetsyn_cell_kernel<<<grid, block>>>(x, w, rho, hz, hIsyn, hIr,
                                        z_out, Isyn_o, Ir_out);
}

// round 3
// speedup vs baseline: 1.1045x; 1.0838x over previous
#include <cuda_runtime.h>

// Problem constants (fixed by setup_inputs)
#define B_  64
#define NO_ 1024
#define NI_ 1024
#define NB  8          // batches per block

// RHO_R = exp(-DT/TAU_R) = exp(-0.05)
__device__ __constant__ float kRhoR = 0.95122942450071400910f;

// Block = (j, tile of NB batches). 256 threads x float4 = 1024 = NI.
// Two-phase body: ALL NB streaming loads issued first (MLP=8), then
// compute + store. rho/w row loaded once and reused across NB batches.
__global__ void __launch_bounds__(256)
hetsyn_cell_kernel(const float* __restrict__ x,      // (B, NI)
                   const float* __restrict__ w,      // (NO, NI)
                   const float* __restrict__ rho,    // (NO, NI)
                   const float* __restrict__ hz,     // (B, NO)
                   const float* __restrict__ hIsyn,  // (B, NO, NI)
                   const float* __restrict__ hIr,    // (B, NO)
                   float* __restrict__ z_out,        // (B, NO)
                   float* __restrict__ Isyn_out,     // (B, NO, NI)
                   float* __restrict__ Ir_out)       // (B, NO)
{
    const int j  = blockIdx.x;          // output neuron row
    const int b0 = blockIdx.y * NB;     // first batch of this tile
    const int t  = threadIdx.x;         // 0..255

    const size_t wrow = (size_t)j * NI_;
    const float4 rv = __ldg(reinterpret_cast<const float4*>(rho + wrow) + t);
    const float4 wv = __ldg(reinterpret_cast<const float4*>(w   + wrow) + t);

    // ---- Phase 1: front-batch all NB streaming loads (high MLP) ----
    float4 hv[NB];
    {
        const float4* p = reinterpret_cast<const float4*>(
            hIsyn + ((size_t)b0 * NO_ + j) * (size_t)NI_) + t;
        #pragma unroll
        for (int bb = 0; bb < NB; ++bb) {
            hv[bb] = __ldcs(p);
            p += (size_t)NO_ * NI_ / 4;   // next batch, same row j
        }
    }

    // ---- Phase 2: compute, store, partial sums ----
    float psum[NB];
    {
        float4* q = reinterpret_cast<float4*>(
            Isyn_out + ((size_t)b0 * NO_ + j) * (size_t)NI_) + t;
        #pragma unroll
        for (int bb = 0; bb < NB; ++bb) {
            const float4 xv = __ldg(
                reinterpret_cast<const float4*>(x + (size_t)(b0 + bb) * NI_) + t);

            float4 Is;
            Is.x = fmaf(rv.x, hv[bb].x, wv.x * xv.x);
            Is.y = fmaf(rv.y, hv[bb].y, wv.y * xv.y);
            Is.z = fmaf(rv.z, hv[bb].z, wv.z * xv.z);
            Is.w = fmaf(rv.w, hv[bb].w, wv.w * xv.w);

            __stcs(q, Is);
            q += (size_t)NO_ * NI_ / 4;

            psum[bb] = (Is.x + Is.y) + (Is.z + Is.w);
        }
    }

    // Warp-level reduction of each of the NB partial sums
    #pragma unroll
    for (int bb = 0; bb < NB; ++bb) {
        #pragma unroll
        for (int off = 16; off > 0; off >>= 1)
            psum[bb] += __shfl_down_sync(0xFFFFFFFFu, psum[bb], off);
    }

    __shared__ float wsum[8][NB];   // [warp][batch]
    const int lane = t & 31;
    const int warp = t >> 5;
    if (lane == 0) {
        #pragma unroll
        for (int bb = 0; bb < NB; ++bb) wsum[warp][bb] = psum[bb];
    }
    __syncthreads();

    if (t < NB) {
        float v_in = 0.0f;
        #pragma unroll
        for (int k = 0; k < 8; ++k) v_in += wsum[k][t];

        const int b    = b0 + t;
        const int oidx = b * NO_ + j;

        const float Ir = fmaf(kRhoR, hIr[oidx], hz[oidx]);
        Ir_out[oidx] = Ir;
        // v = v_in - THR*Ir; z = (v - THR >= 0), THR = 1
        z_out[oidx]  = (v_in - Ir - 1.0f >= 0.0f) ? 1.0f : 0.0f;
    }
}

extern "C" void kernel_launch(void* const* d_in, const int* in_sizes, int n_in,
                              void* d_out, int out_size)
{
    // Input order per setup_inputs: x, w, rho, hz, hIsyn, hIr
    const float* x     = (const float*)d_in[0];
    const float* w     = (const float*)d_in[1];
    const float* rho   = (const float*)d_in[2];
    const float* hz    = (const float*)d_in[3];
    const float* hIsyn = (const float*)d_in[4];
    const float* hIr   = (const float*)d_in[5];

    // Output tuple (z, Isyn, Ir) flattened + concatenated
    float* out    = (float*)d_out;
    float* z_out  = out;
    float* Isyn_o = out + (size_t)B_ * NO_;
    float* Ir_out = out + (size_t)B_ * NO_ + (size_t)B_ * NO_ * NI_;

    dim3 grid(NO_, B_ / NB);   // (1024, 8) = 8192 blocks
    dim3 block(256);
    hetsyn_cell_kernel<<<grid, block>>>(x, w, rho, hz, hIsyn, hIr,
                                        z_out, Isyn_o, Ir_out);
}